// round 10
// baseline (speedup 1.0000x reference)
#include <cuda_runtime.h>
#include <cuda_fp16.h>
#include <cstdint>

#define B_ 4
#define C_ 128
#define N_ 4096
#define M_ 4096
#define TQ 128
#define TK 64
#define NTH (M_ / TK / 2)   // 32 tiles per key-half

// scratch (allocation-free rule: __device__ globals)
__device__ __align__(256) __half g_q[(size_t)B_ * N_ * C_];  // [b][n][c], scaled log2e/sqrt(C)
__device__ __align__(256) __half g_k[(size_t)B_ * M_ * C_];  // [b][m][c]
__device__ __align__(256) __half g_v[(size_t)B_ * M_ * C_];  // [b][m][c]
__device__ __align__(256) __half g_op[2][(size_t)B_ * N_ * C_]; // partial O per key-half
__device__ float g_rs[2][(size_t)B_ * N_];                      // partial row sums
__device__ int   g_tick[B_ * (N_ / TQ)];                        // merge tickets

__device__ __forceinline__ uint32_t smem_u32(const void* p) {
    uint32_t a;
    asm("{ .reg .u64 t; cvta.to.shared.u64 t, %1; cvt.u32.u64 %0, t; }" : "=r"(a) : "l"(p));
    return a;
}
__device__ __forceinline__ void cp_async16(uint32_t dst, const void* src) {
    asm volatile("cp.async.cg.shared.global [%0], [%1], 16;" :: "r"(dst), "l"(src));
}
__device__ __forceinline__ void ldsm4(uint32_t a, uint32_t& r0, uint32_t& r1, uint32_t& r2, uint32_t& r3) {
    asm volatile("ldmatrix.sync.aligned.m8n8.x4.shared.b16 {%0,%1,%2,%3}, [%4];"
                 : "=r"(r0), "=r"(r1), "=r"(r2), "=r"(r3) : "r"(a));
}
__device__ __forceinline__ void ldsm4t(uint32_t a, uint32_t& r0, uint32_t& r1, uint32_t& r2, uint32_t& r3) {
    asm volatile("ldmatrix.sync.aligned.m8n8.x4.trans.shared.b16 {%0,%1,%2,%3}, [%4];"
                 : "=r"(r0), "=r"(r1), "=r"(r2), "=r"(r3) : "r"(a));
}
__device__ __forceinline__ void mma_h(uint32_t* c, const uint32_t* a, uint32_t b0, uint32_t b1) {
    asm volatile("mma.sync.aligned.m16n8k16.row.col.f16.f16.f16.f16 "
                 "{%0,%1}, {%2,%3,%4,%5}, {%6,%7}, {%0,%1};"
                 : "+r"(c[0]), "+r"(c[1])
                 : "r"(a[0]), "r"(a[1]), "r"(a[2]), "r"(a[3]), "r"(b0), "r"(b1));
}
__device__ __forceinline__ uint32_t ex2h2(uint32_t s) {
    uint32_t d;
    asm("ex2.approx.f16x2 %0, %1;" : "=r"(d) : "r"(s));
    return d;
}
__device__ __forceinline__ uint32_t hadd2u(uint32_t a, uint32_t b) {
    __half2 r = __hadd2(*reinterpret_cast<__half2*>(&a), *reinterpret_cast<__half2*>(&b));
    return *reinterpret_cast<uint32_t*>(&r);
}
__device__ __forceinline__ float hsum2(uint32_t a) {
    float2 f = __half22float2(*reinterpret_cast<__half2*>(&a));
    return f.x + f.y;
}
__device__ __forceinline__ uint32_t packh2(float lo, float hi) {
    __half2 h = __floats2half2_rn(lo, hi);
    return *reinterpret_cast<uint32_t*>(&h);
}
__device__ __forceinline__ float2 h2f2(uint32_t v) {
    return __half22float2(*reinterpret_cast<__half2*>(&v));
}

// ---------------------------------------------------------------------------
__global__ void zero_tick() {
    if (threadIdx.x < B_ * (N_ / TQ)) g_tick[threadIdx.x] = 0;
}

// ---------------------------------------------------------------------------
// Fused projection: z=0 -> q = (Wq(x1+Wpos p1))*log2e/rtC; z=1 -> k AND v
// (x2 + p2 read once, both weight matrices resident).
// smem: wps[0,1536) sXa@1536 sXb@18944 sWa@36352 sWb@71168; total 105984.
// ---------------------------------------------------------------------------
#define PROJ_SMEM 105984

__global__ __launch_bounds__(128, 2)
void proj_all(const float* __restrict__ x1, const float* __restrict__ p1,
              const float* __restrict__ x2, const float* __restrict__ p2,
              const float* __restrict__ Wq, const float* __restrict__ Wk,
              const float* __restrict__ Wv, const float* __restrict__ Wpos)
{
    extern __shared__ __align__(16) char smem[];
    const uint32_t sb = smem_u32(smem);
    float* wps = (float*)smem;
    __half* sXa = (__half*)(smem + 1536);
    __half* sXb = (__half*)(smem + 18944);
    __half* sWa = (__half*)(smem + 36352);
    __half* sWb = (__half*)(smem + 71168);

    const int tid = threadIdx.x, lane = tid & 31, w = tid >> 5;
    const int b = blockIdx.y, n0 = blockIdx.x * 64, role = blockIdx.z;

    const float* x = (role == 0) ? x1 : x2;
    const float* p = (role == 0) ? p1 : p2;
    const float* Wa = (role == 0) ? Wq : Wk;
    const float scale = (role == 0) ? 0.12752538963474926f : 1.0f;  // log2e/sqrt(128)

    #pragma unroll
    for (int it = 0; it < 3; it++) wps[tid + it * 128] = Wpos[tid + it * 128];
    #pragma unroll
    for (int it = 0; it < 32; it++) {
        int e4 = tid + it * 128, d = e4 >> 5, c4 = e4 & 31;
        float4 wv = *(const float4*)&Wa[d * 128 + c4 * 4];
        *(uint2*)&sWa[d * 136 + c4 * 4] = make_uint2(packh2(wv.x, wv.y), packh2(wv.z, wv.w));
    }
    if (role == 1) {
        #pragma unroll
        for (int it = 0; it < 32; it++) {
            int e4 = tid + it * 128, d = e4 >> 5, c4 = e4 & 31;
            float4 wv = *(const float4*)&Wv[d * 128 + c4 * 4];
            *(uint2*)&sWb[d * 136 + c4 * 4] = make_uint2(packh2(wv.x, wv.y), packh2(wv.z, wv.w));
        }
    }
    __syncthreads();

    {
        int n = tid & 63, cg = tid >> 6, gn = n0 + n;
        float pp0 = p[(b * 3 + 0) * N_ + gn];
        float pp1 = p[(b * 3 + 1) * N_ + gn];
        float pp2 = p[(b * 3 + 2) * N_ + gn];
        #pragma unroll
        for (int it = 0; it < 32; it++) {
            int c0 = it * 4 + cg * 2;
            float t0 = x[((size_t)(b * C_ + c0)) * N_ + gn];
            float t1 = x[((size_t)(b * C_ + c0 + 1)) * N_ + gn];
            float q0 = t0 + wps[c0*3]*pp0 + wps[c0*3+1]*pp1 + wps[c0*3+2]*pp2;
            float q1 = t1 + wps[(c0+1)*3]*pp0 + wps[(c0+1)*3+1]*pp1 + wps[(c0+1)*3+2]*pp2;
            *(uint32_t*)&sXa[n * 136 + c0] = packh2(q0 * scale, q1 * scale);
            if (role == 1)
                *(uint32_t*)&sXb[n * 136 + c0] = packh2(t0, t1);  // v input: raw x2
        }
    }
    __syncthreads();

    const uint32_t xaoff = sb + 1536u  + (uint32_t)(w * 16 + (lane & 15)) * 272 + ((lane >> 4) & 1) * 16;
    const uint32_t xboff = sb + 18944u + (uint32_t)(w * 16 + (lane & 15)) * 272 + ((lane >> 4) & 1) * 16;
    const uint32_t waoff = sb + 36352u + (uint32_t)(lane & 15) * 272 + ((lane >> 4) & 1) * 16;
    const uint32_t wboff = sb + 71168u + (uint32_t)(lane & 15) * 272 + ((lane >> 4) & 1) * 16;

    uint32_t cfA[16][2], cfB[16][2];
    #pragma unroll
    for (int g = 0; g < 16; g++) { cfA[g][0]=0u; cfA[g][1]=0u; cfB[g][0]=0u; cfB[g][1]=0u; }

    #pragma unroll
    for (int kc = 0; kc < 8; kc++) {
        uint32_t aa[4];
        ldsm4(xaoff + kc * 32, aa[0], aa[1], aa[2], aa[3]);
        uint32_t ab[4];
        if (role == 1) ldsm4(xboff + kc * 32, ab[0], ab[1], ab[2], ab[3]);
        #pragma unroll
        for (int dp = 0; dp < 8; dp++) {
            uint32_t r0, r1, r2, r3;
            ldsm4(waoff + dp * 4352 + kc * 32, r0, r1, r2, r3);
            mma_h(cfA[2 * dp],     aa, r0, r2);
            mma_h(cfA[2 * dp + 1], aa, r1, r3);
            if (role == 1) {
                ldsm4(wboff + dp * 4352 + kc * 32, r0, r1, r2, r3);
                mma_h(cfB[2 * dp],     ab, r0, r2);
                mma_h(cfB[2 * dp + 1], ab, r1, r3);
            }
        }
    }

    const int pt = n0 + w * 16 + (lane >> 2);
    __half* outA = (role == 0) ? g_q : g_k;
    #pragma unroll
    for (int dp = 0; dp < 8; dp++)
        #pragma unroll
        for (int hh = 0; hh < 2; hh++) {
            int d = dp * 16 + hh * 8 + (lane & 3) * 2;
            *(uint32_t*)&outA[((size_t)(b * N_ + pt)) * C_ + d]     = cfA[2 * dp + hh][0];
            *(uint32_t*)&outA[((size_t)(b * N_ + pt + 8)) * C_ + d] = cfA[2 * dp + hh][1];
            if (role == 1) {
                *(uint32_t*)&g_v[((size_t)(b * N_ + pt)) * C_ + d]     = cfB[2 * dp + hh][0];
                *(uint32_t*)&g_v[((size_t)(b * N_ + pt + 8)) * C_ + d] = cfB[2 * dp + hh][1];
            }
        }
}

// ---------------------------------------------------------------------------
// fp16 flash attention, TQ=128, key-split z=2. 4 warps, warp owns 32 q-rows.
// Softmax of each 32-key half interleaved with PV of the other half.
// Last-finishing kh-CTA merges partials (+x1 residual) and writes output.
// smem = Q[0,34816) K0 K1 V0 V1 (4x17408) = 104448 -> 2 CTAs/SM.
// ---------------------------------------------------------------------------
#define ATTN_SMEM 104448

__global__ __launch_bounds__(128, 2)
void attn_h(const float* __restrict__ x1, float* __restrict__ outp)
{
    extern __shared__ __align__(16) char smem[];
    const uint32_t sb = smem_u32(smem);
    const int tid = threadIdx.x, lane = tid & 31, w = tid >> 5;
    const int b = blockIdx.y, n0 = blockIdx.x * TQ, kh = blockIdx.z;
    const int mbase = kh * (M_ / 2);

    const uint32_t SQ = sb;
    const uint32_t SK0 = sb + 34816u, SK1 = sb + 52224u;
    const uint32_t SV0 = sb + 69632u, SV1 = sb + 87040u;

    // prologue: Q (128 rows) + K(0) + V(0)
    #pragma unroll
    for (int it = 0; it < 16; it++) {
        int idx = tid + it * 128, r = idx >> 4, ch = idx & 15;
        cp_async16(SQ + r * 272 + ch * 16, g_q + ((size_t)(b * N_ + n0 + r)) * C_ + ch * 8);
    }
    #pragma unroll
    for (int it = 0; it < 8; it++) {
        int idx = tid + it * 128, r = idx >> 4, ch = idx & 15;
        cp_async16(SK0 + r * 272 + ch * 16, g_k + ((size_t)(b * M_ + mbase + r)) * C_ + ch * 8);
    }
    #pragma unroll
    for (int it = 0; it < 8; it++) {
        int idx = tid + it * 128, r = idx >> 4, ch = idx & 15;
        cp_async16(SV0 + r * 272 + ch * 16, g_v + ((size_t)(b * M_ + mbase + r)) * C_ + ch * 8);
    }
    asm volatile("cp.async.commit_group;" ::: "memory");
    asm volatile("cp.async.wait_group 0;" ::: "memory");
    __syncthreads();

    // Q fragments: 2 row-groups x 8 k-chunks
    uint32_t qf[8][2][4];
    #pragma unroll
    for (int g = 0; g < 2; g++) {
        const uint32_t qoff = SQ + (uint32_t)(w * 32 + g * 16 + (lane & 15)) * 272
                            + ((lane >> 4) & 1) * 16;
        #pragma unroll
        for (int kc = 0; kc < 8; kc++)
            ldsm4(qoff + kc * 32, qf[kc][g][0], qf[kc][g][1], qf[kc][g][2], qf[kc][g][3]);
    }
    const uint32_t koff = (uint32_t)(lane & 15) * 272 + ((lane >> 4) & 1) * 16;

    uint32_t og[2][16][2];
    #pragma unroll
    for (int g = 0; g < 2; g++)
        #pragma unroll
        for (int q = 0; q < 16; q++) { og[g][q][0] = 0u; og[g][q][1] = 0u; }
    float rsA[2] = {0.f, 0.f}, rsB[2] = {0.f, 0.f};

    #pragma unroll 1
    for (int j = 0; j < NTH; j++) {
        if (j > 0) {
            asm volatile("cp.async.wait_group 0;" ::: "memory");
            __syncthreads();
        }

        if (j + 1 < NTH) {
            const uint32_t kb1 = (j & 1) ? SK0 : SK1;
            const uint32_t vb1 = (j & 1) ? SV0 : SV1;
            const int m1 = mbase + (j + 1) * TK;
            #pragma unroll
            for (int it = 0; it < 8; it++) {
                int idx = tid + it * 128, r = idx >> 4, ch = idx & 15;
                cp_async16(kb1 + r * 272 + ch * 16, g_k + ((size_t)(b * M_ + m1 + r)) * C_ + ch * 8);
            }
            #pragma unroll
            for (int it = 0; it < 8; it++) {
                int idx = tid + it * 128, r = idx >> 4, ch = idx & 15;
                cp_async16(vb1 + r * 272 + ch * 16, g_v + ((size_t)(b * M_ + m1 + r)) * C_ + ch * 8);
            }
            asm volatile("cp.async.commit_group;" ::: "memory");
        }

        const uint32_t kb = (j & 1) ? SK1 : SK0;
        const uint32_t vb = (j & 1) ? SV1 : SV0;

        // S = Q K^T (64 keys x 32 rows), f16 accum; each K frag feeds 4 MMAs
        uint32_t s[2][8][2];
        #pragma unroll
        for (int g = 0; g < 2; g++)
            #pragma unroll
            for (int q = 0; q < 8; q++) { s[g][q][0] = 0u; s[g][q][1] = 0u; }
        #pragma unroll
        for (int kc = 0; kc < 8; kc++) {
            #pragma unroll
            for (int mg = 0; mg < 4; mg++) {
                uint32_t r0, r1, r2, r3;
                ldsm4(kb + mg * 4352 + kc * 32 + koff, r0, r1, r2, r3);
                #pragma unroll
                for (int g = 0; g < 2; g++) {
                    mma_h(s[g][2 * mg],     qf[kc][g], r0, r2);
                    mma_h(s[g][2 * mg + 1], qf[kc][g], r1, r3);
                }
            }
        }

        // two 32-key halves: softmax(h) then PV(h); ex2 of h=1 overlaps PV(h=0)
        #pragma unroll
        for (int h = 0; h < 2; h++) {
            #pragma unroll
            for (int g = 0; g < 2; g++) {
                #pragma unroll
                for (int q = 4 * h; q < 4 * h + 4; q++) {
                    s[g][q][0] = ex2h2(s[g][q][0]);
                    s[g][q][1] = ex2h2(s[g][q][1]);
                }
                uint32_t tA = hadd2u(hadd2u(s[g][4*h][0], s[g][4*h+1][0]),
                                     hadd2u(s[g][4*h+2][0], s[g][4*h+3][0]));
                uint32_t tB = hadd2u(hadd2u(s[g][4*h][1], s[g][4*h+1][1]),
                                     hadd2u(s[g][4*h+2][1], s[g][4*h+3][1]));
                rsA[g] += hsum2(tA);
                rsB[g] += hsum2(tB);
            }
            #pragma unroll
            for (int km = 2 * h; km < 2 * h + 2; km++) {
                uint32_t a0[4] = { s[0][2*km][0], s[0][2*km][1], s[0][2*km+1][0], s[0][2*km+1][1] };
                uint32_t a1[4] = { s[1][2*km][0], s[1][2*km][1], s[1][2*km+1][0], s[1][2*km+1][1] };
                #pragma unroll
                for (int cp = 0; cp < 8; cp++) {
                    uint32_t r0, r1, r2, r3;
                    ldsm4t(vb + km * 4352 + cp * 32 + koff, r0, r1, r2, r3);
                    mma_h(og[0][2 * cp],     a0, r0, r1);
                    mma_h(og[0][2 * cp + 1], a0, r2, r3);
                    mma_h(og[1][2 * cp],     a1, r0, r1);
                    mma_h(og[1][2 * cp + 1], a1, r2, r3);
                }
            }
        }
    }

    // quad-reduce row sums
    #pragma unroll
    for (int g = 0; g < 2; g++) {
        rsA[g] += __shfl_xor_sync(0xffffffffu, rsA[g], 1);
        rsA[g] += __shfl_xor_sync(0xffffffffu, rsA[g], 2);
        rsB[g] += __shfl_xor_sync(0xffffffffu, rsB[g], 1);
        rsB[g] += __shfl_xor_sync(0xffffffffu, rsB[g], 2);
    }

    // publish partials
    #pragma unroll
    for (int g = 0; g < 2; g++) {
        const int rA = w * 32 + g * 16 + (lane >> 2);
        if ((lane & 3) == 0) {
            g_rs[kh][(size_t)b * N_ + n0 + rA]     = rsA[g];
            g_rs[kh][(size_t)b * N_ + n0 + rA + 8] = rsB[g];
        }
        #pragma unroll
        for (int cg = 0; cg < 16; cg++) {
            int c = cg * 8 + (lane & 3) * 2;
            *(uint32_t*)&g_op[kh][((size_t)(b * N_ + n0 + rA)) * C_ + c]     = og[g][cg][0];
            *(uint32_t*)&g_op[kh][((size_t)(b * N_ + n0 + rA + 8)) * C_ + c] = og[g][cg][1];
        }
    }
    __threadfence();
    __syncthreads();

    __shared__ int s_old;
    if (tid == 0) s_old = atomicAdd(&g_tick[(b << 5) | blockIdx.x], 1);
    __syncthreads();
    if (s_old == 0) return;     // first finisher: partner will merge
    __threadfence();            // acquire: partner's writes now visible

    // stage x1 [c][n_local 0..127] f32 into K/V region (128 x 132 floats)
    float* x1s = (float*)(smem + 34816);
    #pragma unroll
    for (int it = 0; it < 32; it++) {
        int idx = tid + it * 128, r = idx >> 5, ch = idx & 31;
        *(float4*)(x1s + r * 132 + ch * 4) =
            *(const float4*)(x1 + ((size_t)(b * C_ + r)) * N_ + n0 + ch * 4);
    }
    __syncthreads();

    const int oh = kh ^ 1;
    #pragma unroll
    for (int g = 0; g < 2; g++) {
        const int rA = w * 32 + g * 16 + (lane >> 2);
        const float invA = 1.0f / (g_rs[0][(size_t)b * N_ + n0 + rA]
                                 + g_rs[1][(size_t)b * N_ + n0 + rA]);
        const float invB = 1.0f / (g_rs[0][(size_t)b * N_ + n0 + rA + 8]
                                 + g_rs[1][(size_t)b * N_ + n0 + rA + 8]);
        #pragma unroll
        for (int cg = 0; cg < 16; cg++) {
            int c = cg * 8 + (lane & 3) * 2;
            uint32_t m0 = *(uint32_t*)&g_op[oh][((size_t)(b * N_ + n0 + rA)) * C_ + c];
            uint32_t m1 = *(uint32_t*)&g_op[oh][((size_t)(b * N_ + n0 + rA + 8)) * C_ + c];
            float2 f0 = h2f2(og[g][cg][0]), e0 = h2f2(m0);
            float2 f1 = h2f2(og[g][cg][1]), e1 = h2f2(m1);
            float2 oA, oB;
            oA.x = (f0.x + e0.x) * invA + x1s[c * 132 + rA];
            oA.y = (f0.y + e0.y) * invA + x1s[(c + 1) * 132 + rA];
            oB.x = (f1.x + e1.x) * invB + x1s[c * 132 + rA + 8];
            oB.y = (f1.y + e1.y) * invB + x1s[(c + 1) * 132 + rA + 8];
            *(float2*)&outp[((size_t)(b * N_ + n0 + rA)) * C_ + c]     = oA;
            *(float2*)&outp[((size_t)(b * N_ + n0 + rA + 8)) * C_ + c] = oB;
        }
    }
}

// ---------------------------------------------------------------------------
extern "C" void kernel_launch(void* const* d_in, const int* in_sizes, int n_in,
                              void* d_out, int out_size)
{
    const float* x1   = (const float*)d_in[0];
    const float* p1   = (const float*)d_in[1];
    const float* x2   = (const float*)d_in[2];
    const float* p2   = (const float*)d_in[3];
    const float* Wq   = (const float*)d_in[4];
    const float* Wk   = (const float*)d_in[5];
    const float* Wv   = (const float*)d_in[6];
    const float* Wpos = (const float*)d_in[7];
    float* out = (float*)d_out;

    cudaFuncSetAttribute(proj_all, cudaFuncAttributeMaxDynamicSharedMemorySize, PROJ_SMEM);
    cudaFuncSetAttribute(attn_h,   cudaFuncAttributeMaxDynamicSharedMemorySize, ATTN_SMEM);

    zero_tick<<<1, 128>>>();

    dim3 gproj(64, B_, 2), bproj(128);
    proj_all<<<gproj, bproj, PROJ_SMEM>>>(x1, p1, x2, p2, Wq, Wk, Wv, Wpos);

    dim3 gattn(N_ / TQ, B_, 2), battn(128);
    attn_h<<<gattn, battn, ATTN_SMEM>>>(x1, out);
}

// round 11
// speedup vs baseline: 1.0353x; 1.0353x over previous
#include <cuda_runtime.h>
#include <cuda_fp16.h>
#include <cstdint>

#define B_ 4
#define C_ 128
#define N_ 4096
#define M_ 4096
#define TQ 128
#define TK 64
#define NTH (M_ / TK / 2)   // 32 tiles per key-half

// scratch (allocation-free rule: __device__ globals)
__device__ __align__(256) __half g_q[(size_t)B_ * N_ * C_];  // [b][n][c], scaled log2e/sqrt(C)
__device__ __align__(256) __half g_k[(size_t)B_ * M_ * C_];  // [b][m][c]
__device__ __align__(256) __half g_v[(size_t)B_ * M_ * C_];  // [b][m][c]
__device__ __align__(256) __half g_w[3][C_ * C_];            // f16 weights [d][c]
__device__ __align__(256) __half g_op[2][(size_t)B_ * N_ * C_]; // partial O per key-half
__device__ float g_rs[2][(size_t)B_ * N_];                      // partial row sums

__device__ __forceinline__ uint32_t smem_u32(const void* p) {
    uint32_t a;
    asm("{ .reg .u64 t; cvta.to.shared.u64 t, %1; cvt.u32.u64 %0, t; }" : "=r"(a) : "l"(p));
    return a;
}
__device__ __forceinline__ void cp_async16(uint32_t dst, const void* src) {
    asm volatile("cp.async.cg.shared.global [%0], [%1], 16;" :: "r"(dst), "l"(src));
}
__device__ __forceinline__ void ldsm4(uint32_t a, uint32_t& r0, uint32_t& r1, uint32_t& r2, uint32_t& r3) {
    asm volatile("ldmatrix.sync.aligned.m8n8.x4.shared.b16 {%0,%1,%2,%3}, [%4];"
                 : "=r"(r0), "=r"(r1), "=r"(r2), "=r"(r3) : "r"(a));
}
__device__ __forceinline__ void ldsm4t(uint32_t a, uint32_t& r0, uint32_t& r1, uint32_t& r2, uint32_t& r3) {
    asm volatile("ldmatrix.sync.aligned.m8n8.x4.trans.shared.b16 {%0,%1,%2,%3}, [%4];"
                 : "=r"(r0), "=r"(r1), "=r"(r2), "=r"(r3) : "r"(a));
}
__device__ __forceinline__ void mma_h(uint32_t* c, const uint32_t* a, uint32_t b0, uint32_t b1) {
    asm volatile("mma.sync.aligned.m16n8k16.row.col.f16.f16.f16.f16 "
                 "{%0,%1}, {%2,%3,%4,%5}, {%6,%7}, {%0,%1};"
                 : "+r"(c[0]), "+r"(c[1])
                 : "r"(a[0]), "r"(a[1]), "r"(a[2]), "r"(a[3]), "r"(b0), "r"(b1));
}
__device__ __forceinline__ uint32_t ex2h2(uint32_t s) {
    uint32_t d;
    asm("ex2.approx.f16x2 %0, %1;" : "=r"(d) : "r"(s));
    return d;
}
__device__ __forceinline__ uint32_t hadd2u(uint32_t a, uint32_t b) {
    __half2 r = __hadd2(*reinterpret_cast<__half2*>(&a), *reinterpret_cast<__half2*>(&b));
    return *reinterpret_cast<uint32_t*>(&r);
}
__device__ __forceinline__ float hsum2(uint32_t a) {
    float2 f = __half22float2(*reinterpret_cast<__half2*>(&a));
    return f.x + f.y;
}
__device__ __forceinline__ uint32_t packh2(float lo, float hi) {
    __half2 h = __floats2half2_rn(lo, hi);
    return *reinterpret_cast<uint32_t*>(&h);
}

// ---------------------------------------------------------------------------
// One-time weight conversion: Wq/Wk/Wv f32 -> f16 [d][c].
// ---------------------------------------------------------------------------
__global__ __launch_bounds__(256)
void wprep(const float* __restrict__ Wq, const float* __restrict__ Wk,
           const float* __restrict__ Wv)
{
    const int r = blockIdx.x;   // 0..2
    const float* W = (r == 0) ? Wq : (r == 1) ? Wk : Wv;
    const int tid = threadIdx.x;
    #pragma unroll
    for (int it = 0; it < 16; it++) {
        int e4 = tid + it * 256;                    // 4096 float4 groups
        float4 wv = *(const float4*)&W[e4 * 4];
        *(uint2*)&g_w[r][e4 * 4] = make_uint2(packh2(wv.x, wv.y), packh2(wv.z, wv.w));
    }
}

// ---------------------------------------------------------------------------
// Projection: grid.z = role. 0: q=(Wq(x1+Wpos p1))*log2e/rtC; 1: k=Wk(x2+Wpos p2);
// 2: v=Wv x2. W cp.async'd (f16, prepped) OVERLAPPED with x convert phase.
// smem: wps[0,1536) sX@1536 (64x272B) sW@18944 (128x272B); total 53760.
// ---------------------------------------------------------------------------
#define PROJ_SMEM (1536 + 17408 + 34816)

__global__ __launch_bounds__(128, 3)
void proj_all(const float* __restrict__ x1, const float* __restrict__ p1,
              const float* __restrict__ x2, const float* __restrict__ p2,
              const float* __restrict__ Wpos)
{
    extern __shared__ __align__(16) char smem[];
    const uint32_t sb = smem_u32(smem);
    float* wps = (float*)smem;
    __half* sX = (__half*)(smem + 1536);

    const int tid = threadIdx.x, lane = tid & 31, w = tid >> 5;
    const int b = blockIdx.y, n0 = blockIdx.x * 64, role = blockIdx.z;

    const float* x = (role == 0) ? x1 : x2;
    const float* p = (role == 0) ? p1 : p2;
    __half* outp   = (role == 0) ? g_q : (role == 1) ? g_k : g_v;
    const bool usepos = (role != 2);
    const float scale = (role == 0) ? 0.12752538963474926f : 1.0f;  // log2e/sqrt(128)

    // async W load (f16, pre-converted) — overlaps the whole x phase below
    #pragma unroll
    for (int it = 0; it < 16; it++) {
        int idx = tid + it * 128, r = idx >> 4, ch = idx & 15;
        cp_async16(sb + 18944u + r * 272 + ch * 16, &g_w[role][r * 128 + ch * 8]);
    }
    asm volatile("cp.async.commit_group;" ::: "memory");

    #pragma unroll
    for (int it = 0; it < 3; it++) wps[tid + it * 128] = Wpos[tid + it * 128];
    __syncthreads();

    {
        int n = tid & 63, cg = tid >> 6, gn = n0 + n;
        float pp0 = 0.f, pp1 = 0.f, pp2 = 0.f;
        if (usepos) {
            pp0 = p[(b * 3 + 0) * N_ + gn];
            pp1 = p[(b * 3 + 1) * N_ + gn];
            pp2 = p[(b * 3 + 2) * N_ + gn];
        }
        #pragma unroll
        for (int it = 0; it < 32; it++) {
            int c0 = it * 4 + cg * 2;
            float t0 = x[((size_t)(b * C_ + c0)) * N_ + gn];
            float t1 = x[((size_t)(b * C_ + c0 + 1)) * N_ + gn];
            if (usepos) {
                t0 += wps[c0*3]*pp0 + wps[c0*3+1]*pp1 + wps[c0*3+2]*pp2;
                t1 += wps[(c0+1)*3]*pp0 + wps[(c0+1)*3+1]*pp1 + wps[(c0+1)*3+2]*pp2;
            }
            *(uint32_t*)&sX[n * 136 + c0] = packh2(t0 * scale, t1 * scale);
        }
    }
    asm volatile("cp.async.wait_group 0;" ::: "memory");
    __syncthreads();

    uint32_t cf[16][2];
    #pragma unroll
    for (int g = 0; g < 16; g++) { cf[g][0] = 0u; cf[g][1] = 0u; }
    const uint32_t aoff = sb + 1536u  + (uint32_t)(w * 16 + (lane & 15)) * 272 + ((lane >> 4) & 1) * 16;
    const uint32_t woff = sb + 18944u + (uint32_t)(lane & 15) * 272 + ((lane >> 4) & 1) * 16;

    #pragma unroll
    for (int kc = 0; kc < 8; kc++) {
        uint32_t a[4];
        ldsm4(aoff + kc * 32, a[0], a[1], a[2], a[3]);
        #pragma unroll
        for (int dp = 0; dp < 8; dp++) {
            uint32_t r0, r1, r2, r3;
            ldsm4(woff + dp * 4352 + kc * 32, r0, r1, r2, r3);
            mma_h(cf[2 * dp],     a, r0, r2);
            mma_h(cf[2 * dp + 1], a, r1, r3);
        }
    }

    const int pt = n0 + w * 16 + (lane >> 2);
    #pragma unroll
    for (int dp = 0; dp < 8; dp++)
        #pragma unroll
        for (int hh = 0; hh < 2; hh++) {
            int d = dp * 16 + hh * 8 + (lane & 3) * 2;
            *(uint32_t*)&outp[((size_t)(b * N_ + pt)) * C_ + d]     = cf[2 * dp + hh][0];
            *(uint32_t*)&outp[((size_t)(b * N_ + pt + 8)) * C_ + d] = cf[2 * dp + hh][1];
        }
}

// ---------------------------------------------------------------------------
// fp16 flash attention (R9, unchanged — measured best): TQ=128, 4 warps,
// warp owns 32 q-rows; key-split z=2; K,V double-buffered; 1 sync/tile.
// smem = Q[0,34816) K0 K1 V0 V1 (4x17408) = 104448 -> 2 CTAs/SM.
// ---------------------------------------------------------------------------
#define ATTN_SMEM 104448

__global__ __launch_bounds__(128, 2)
void attn_h(int dummy)
{
    extern __shared__ __align__(16) char smem[];
    const uint32_t sb = smem_u32(smem);
    const int tid = threadIdx.x, lane = tid & 31, w = tid >> 5;
    const int b = blockIdx.y, n0 = blockIdx.x * TQ, kh = blockIdx.z;
    const int mbase = kh * (M_ / 2);

    const uint32_t SQ = sb;
    const uint32_t SK0 = sb + 34816u, SK1 = sb + 52224u;
    const uint32_t SV0 = sb + 69632u, SV1 = sb + 87040u;

    // prologue: Q (128 rows) + K(0) + V(0)
    #pragma unroll
    for (int it = 0; it < 16; it++) {
        int idx = tid + it * 128, r = idx >> 4, ch = idx & 15;
        cp_async16(SQ + r * 272 + ch * 16, g_q + ((size_t)(b * N_ + n0 + r)) * C_ + ch * 8);
    }
    #pragma unroll
    for (int it = 0; it < 8; it++) {
        int idx = tid + it * 128, r = idx >> 4, ch = idx & 15;
        cp_async16(SK0 + r * 272 + ch * 16, g_k + ((size_t)(b * M_ + mbase + r)) * C_ + ch * 8);
    }
    #pragma unroll
    for (int it = 0; it < 8; it++) {
        int idx = tid + it * 128, r = idx >> 4, ch = idx & 15;
        cp_async16(SV0 + r * 272 + ch * 16, g_v + ((size_t)(b * M_ + mbase + r)) * C_ + ch * 8);
    }
    asm volatile("cp.async.commit_group;" ::: "memory");
    asm volatile("cp.async.wait_group 0;" ::: "memory");
    __syncthreads();

    // Q fragments: 2 row-groups x 8 k-chunks
    uint32_t qf[8][2][4];
    #pragma unroll
    for (int g = 0; g < 2; g++) {
        const uint32_t qoff = SQ + (uint32_t)(w * 32 + g * 16 + (lane & 15)) * 272
                            + ((lane >> 4) & 1) * 16;
        #pragma unroll
        for (int kc = 0; kc < 8; kc++)
            ldsm4(qoff + kc * 32, qf[kc][g][0], qf[kc][g][1], qf[kc][g][2], qf[kc][g][3]);
    }
    const uint32_t koff = (uint32_t)(lane & 15) * 272 + ((lane >> 4) & 1) * 16;

    uint32_t og[2][16][2];
    #pragma unroll
    for (int g = 0; g < 2; g++)
        #pragma unroll
        for (int q = 0; q < 16; q++) { og[g][q][0] = 0u; og[g][q][1] = 0u; }
    float rsA[2] = {0.f, 0.f}, rsB[2] = {0.f, 0.f};

    #pragma unroll 1
    for (int j = 0; j < NTH; j++) {
        if (j > 0) {
            asm volatile("cp.async.wait_group 0;" ::: "memory");
            __syncthreads();
        }

        if (j + 1 < NTH) {
            const uint32_t kb1 = (j & 1) ? SK0 : SK1;
            const uint32_t vb1 = (j & 1) ? SV0 : SV1;
            const int m1 = mbase + (j + 1) * TK;
            #pragma unroll
            for (int it = 0; it < 8; it++) {
                int idx = tid + it * 128, r = idx >> 4, ch = idx & 15;
                cp_async16(kb1 + r * 272 + ch * 16, g_k + ((size_t)(b * M_ + m1 + r)) * C_ + ch * 8);
            }
            #pragma unroll
            for (int it = 0; it < 8; it++) {
                int idx = tid + it * 128, r = idx >> 4, ch = idx & 15;
                cp_async16(vb1 + r * 272 + ch * 16, g_v + ((size_t)(b * M_ + m1 + r)) * C_ + ch * 8);
            }
            asm volatile("cp.async.commit_group;" ::: "memory");
        }

        const uint32_t kb = (j & 1) ? SK1 : SK0;
        const uint32_t vb = (j & 1) ? SV1 : SV0;

        // S = Q K^T (64 keys x 32 rows), f16 accum; each K frag feeds 4 MMAs
        uint32_t s[2][8][2];
        #pragma unroll
        for (int g = 0; g < 2; g++)
            #pragma unroll
            for (int q = 0; q < 8; q++) { s[g][q][0] = 0u; s[g][q][1] = 0u; }
        #pragma unroll
        for (int kc = 0; kc < 8; kc++) {
            #pragma unroll
            for (int mg = 0; mg < 4; mg++) {
                uint32_t r0, r1, r2, r3;
                ldsm4(kb + mg * 4352 + kc * 32 + koff, r0, r1, r2, r3);
                #pragma unroll
                for (int g = 0; g < 2; g++) {
                    mma_h(s[g][2 * mg],     qf[kc][g], r0, r2);
                    mma_h(s[g][2 * mg + 1], qf[kc][g], r1, r3);
                }
            }
        }

        // P = exp2(S) (log2-domain, no max); row sums
        #pragma unroll
        for (int g = 0; g < 2; g++) {
            #pragma unroll
            for (int q = 0; q < 8; q++) { s[g][q][0] = ex2h2(s[g][q][0]); s[g][q][1] = ex2h2(s[g][q][1]); }
            uint32_t tA = hadd2u(hadd2u(hadd2u(s[g][0][0], s[g][1][0]), hadd2u(s[g][2][0], s[g][3][0])),
                                 hadd2u(hadd2u(s[g][4][0], s[g][5][0]), hadd2u(s[g][6][0], s[g][7][0])));
            uint32_t tB = hadd2u(hadd2u(hadd2u(s[g][0][1], s[g][1][1]), hadd2u(s[g][2][1], s[g][3][1])),
                                 hadd2u(hadd2u(s[g][4][1], s[g][5][1]), hadd2u(s[g][6][1], s[g][7][1])));
            rsA[g] += hsum2(tA);
            rsB[g] += hsum2(tB);
        }

        // O += P V (S C-frags reused as A-frags; V frag feeds 4 MMAs)
        #pragma unroll
        for (int km = 0; km < 4; km++) {
            uint32_t a0[4] = { s[0][2*km][0], s[0][2*km][1], s[0][2*km+1][0], s[0][2*km+1][1] };
            uint32_t a1[4] = { s[1][2*km][0], s[1][2*km][1], s[1][2*km+1][0], s[1][2*km+1][1] };
            #pragma unroll
            for (int cp = 0; cp < 8; cp++) {
                uint32_t r0, r1, r2, r3;
                ldsm4t(vb + km * 4352 + cp * 32 + koff, r0, r1, r2, r3);
                mma_h(og[0][2 * cp],     a0, r0, r1);
                mma_h(og[0][2 * cp + 1], a0, r2, r3);
                mma_h(og[1][2 * cp],     a1, r0, r1);
                mma_h(og[1][2 * cp + 1], a1, r2, r3);
            }
        }
    }

    // quad-reduce row sums; write partials
    #pragma unroll
    for (int g = 0; g < 2; g++) {
        rsA[g] += __shfl_xor_sync(0xffffffffu, rsA[g], 1);
        rsA[g] += __shfl_xor_sync(0xffffffffu, rsA[g], 2);
        rsB[g] += __shfl_xor_sync(0xffffffffu, rsB[g], 1);
        rsB[g] += __shfl_xor_sync(0xffffffffu, rsB[g], 2);
    }

    #pragma unroll
    for (int g = 0; g < 2; g++) {
        const int rA = w * 32 + g * 16 + (lane >> 2);
        if ((lane & 3) == 0) {
            g_rs[kh][(size_t)b * N_ + n0 + rA]     = rsA[g];
            g_rs[kh][(size_t)b * N_ + n0 + rA + 8] = rsB[g];
        }
        #pragma unroll
        for (int cg = 0; cg < 16; cg++) {
            int c = cg * 8 + (lane & 3) * 2;
            *(uint32_t*)&g_op[kh][((size_t)(b * N_ + n0 + rA)) * C_ + c]     = og[g][cg][0];
            *(uint32_t*)&g_op[kh][((size_t)(b * N_ + n0 + rA + 8)) * C_ + c] = og[g][cg][1];
        }
    }
}

// ---------------------------------------------------------------------------
// Merge: out[b][n][c] = (O0+O1)[n][c] / (rs0+rs1)[n] + x1[b][c][n].
// ---------------------------------------------------------------------------
__global__ __launch_bounds__(256)
void merge_out(const float* __restrict__ x1, float* __restrict__ outp)
{
    __shared__ float x1s[128 * 68];
    const int tid = threadIdx.x;
    const int b = blockIdx.y, n0 = blockIdx.x * 64;

    #pragma unroll
    for (int it = 0; it < 8; it++) {
        int idx = tid + it * 256, r = idx >> 4, cc = idx & 15;
        *(float4*)&x1s[r * 68 + cc * 4] =
            *(const float4*)(x1 + ((size_t)(b * C_ + r)) * N_ + n0 + cc * 4);
    }
    __syncthreads();

    const int nl = tid >> 2, n = n0 + nl, chunk = tid & 3;
    const float inv = 1.0f / (g_rs[0][(size_t)b * N_ + n] + g_rs[1][(size_t)b * N_ + n]);

    #pragma unroll
    for (int i = 0; i < 4; i++) {
        int c = chunk * 32 + i * 8;
        uint4 h0 = *(const uint4*)&g_op[0][((size_t)(b * N_ + n)) * C_ + c];
        uint4 h1 = *(const uint4*)&g_op[1][((size_t)(b * N_ + n)) * C_ + c];
        float4 o0, o1;
        float2 f;
        f = __half22float2(*reinterpret_cast<__half2*>(&h0.x));
        { float2 g = __half22float2(*reinterpret_cast<__half2*>(&h1.x)); f.x += g.x; f.y += g.y; }
        o0.x = f.x * inv + x1s[(c + 0) * 68 + nl];
        o0.y = f.y * inv + x1s[(c + 1) * 68 + nl];
        f = __half22float2(*reinterpret_cast<__half2*>(&h0.y));
        { float2 g = __half22float2(*reinterpret_cast<__half2*>(&h1.y)); f.x += g.x; f.y += g.y; }
        o0.z = f.x * inv + x1s[(c + 2) * 68 + nl];
        o0.w = f.y * inv + x1s[(c + 3) * 68 + nl];
        f = __half22float2(*reinterpret_cast<__half2*>(&h0.z));
        { float2 g = __half22float2(*reinterpret_cast<__half2*>(&h1.z)); f.x += g.x; f.y += g.y; }
        o1.x = f.x * inv + x1s[(c + 4) * 68 + nl];
        o1.y = f.y * inv + x1s[(c + 5) * 68 + nl];
        f = __half22float2(*reinterpret_cast<__half2*>(&h0.w));
        { float2 g = __half22float2(*reinterpret_cast<__half2*>(&h1.w)); f.x += g.x; f.y += g.y; }
        o1.z = f.x * inv + x1s[(c + 6) * 68 + nl];
        o1.w = f.y * inv + x1s[(c + 7) * 68 + nl];
        *(float4*)&outp[((size_t)(b * N_ + n)) * C_ + c]     = o0;
        *(float4*)&outp[((size_t)(b * N_ + n)) * C_ + c + 4] = o1;
    }
}

// ---------------------------------------------------------------------------
extern "C" void kernel_launch(void* const* d_in, const int* in_sizes, int n_in,
                              void* d_out, int out_size)
{
    const float* x1   = (const float*)d_in[0];
    const float* p1   = (const float*)d_in[1];
    const float* x2   = (const float*)d_in[2];
    const float* p2   = (const float*)d_in[3];
    const float* Wq   = (const float*)d_in[4];
    const float* Wk   = (const float*)d_in[5];
    const float* Wv   = (const float*)d_in[6];
    const float* Wpos = (const float*)d_in[7];
    float* out = (float*)d_out;

    cudaFuncSetAttribute(proj_all, cudaFuncAttributeMaxDynamicSharedMemorySize, PROJ_SMEM);
    cudaFuncSetAttribute(attn_h,   cudaFuncAttributeMaxDynamicSharedMemorySize, ATTN_SMEM);

    wprep<<<3, 256>>>(Wq, Wk, Wv);

    dim3 gproj(64, B_, 3), bproj(128);
    proj_all<<<gproj, bproj, PROJ_SMEM>>>(x1, p1, x2, p2, Wpos);

    dim3 gattn(N_ / TQ, B_, 2), battn(128);
    attn_h<<<gattn, battn, ATTN_SMEM>>>(0);

    dim3 gmerge(N_ / 64, B_), bmerge(256);
    merge_out<<<gmerge, bmerge>>>(x1, out);
}

// round 12
// speedup vs baseline: 1.0536x; 1.0177x over previous
#include <cuda_runtime.h>
#include <cuda_fp16.h>
#include <cstdint>

#define B_ 4
#define C_ 128
#define N_ 4096
#define M_ 4096
#define TQ 128
#define TK 64
#define NTH (M_ / TK / 2)   // 32 tiles per key-half

// scratch (allocation-free rule: __device__ globals)
__device__ __align__(256) __half g_q[(size_t)B_ * N_ * C_];  // [b][n][c], scaled log2e/sqrt(C)
__device__ __align__(256) __half g_k[(size_t)B_ * M_ * C_];  // [b][m][c]
__device__ __align__(256) __half g_v[(size_t)B_ * M_ * C_];  // [b][m][c]
__device__ __align__(256) __half g_op[2][(size_t)B_ * N_ * C_]; // partial O per key-half
__device__ float g_rs[2][(size_t)B_ * N_];                      // partial row sums

__device__ __forceinline__ uint32_t smem_u32(const void* p) {
    uint32_t a;
    asm("{ .reg .u64 t; cvta.to.shared.u64 t, %1; cvt.u32.u64 %0, t; }" : "=r"(a) : "l"(p));
    return a;
}
__device__ __forceinline__ void cp_async16(uint32_t dst, const void* src) {
    asm volatile("cp.async.cg.shared.global [%0], [%1], 16;" :: "r"(dst), "l"(src));
}
__device__ __forceinline__ void ldsm4(uint32_t a, uint32_t& r0, uint32_t& r1, uint32_t& r2, uint32_t& r3) {
    asm volatile("ldmatrix.sync.aligned.m8n8.x4.shared.b16 {%0,%1,%2,%3}, [%4];"
                 : "=r"(r0), "=r"(r1), "=r"(r2), "=r"(r3) : "r"(a));
}
__device__ __forceinline__ void ldsm4t(uint32_t a, uint32_t& r0, uint32_t& r1, uint32_t& r2, uint32_t& r3) {
    asm volatile("ldmatrix.sync.aligned.m8n8.x4.trans.shared.b16 {%0,%1,%2,%3}, [%4];"
                 : "=r"(r0), "=r"(r1), "=r"(r2), "=r"(r3) : "r"(a));
}
__device__ __forceinline__ void mma_h(uint32_t* c, const uint32_t* a, uint32_t b0, uint32_t b1) {
    asm volatile("mma.sync.aligned.m16n8k16.row.col.f16.f16.f16.f16 "
                 "{%0,%1}, {%2,%3,%4,%5}, {%6,%7}, {%0,%1};"
                 : "+r"(c[0]), "+r"(c[1])
                 : "r"(a[0]), "r"(a[1]), "r"(a[2]), "r"(a[3]), "r"(b0), "r"(b1));
}
__device__ __forceinline__ uint32_t ex2h2(uint32_t s) {
    uint32_t d;
    asm("ex2.approx.f16x2 %0, %1;" : "=r"(d) : "r"(s));
    return d;
}
__device__ __forceinline__ uint32_t hadd2u(uint32_t a, uint32_t b) {
    __half2 r = __hadd2(*reinterpret_cast<__half2*>(&a), *reinterpret_cast<__half2*>(&b));
    return *reinterpret_cast<uint32_t*>(&r);
}
__device__ __forceinline__ float hsum2(uint32_t a) {
    float2 f = __half22float2(*reinterpret_cast<__half2*>(&a));
    return f.x + f.y;
}
__device__ __forceinline__ uint32_t packh2(float lo, float hi) {
    __half2 h = __floats2half2_rn(lo, hi);
    return *reinterpret_cast<uint32_t*>(&h);
}
__device__ __forceinline__ float2 h2f2(uint32_t v) {
    return __half22float2(*reinterpret_cast<__half2*>(&v));
}

// ---------------------------------------------------------------------------
// Fused projection (R9 form — measured 21.5us): grid.z = role.
// 0: q=(Wq(x1+Wpos p1))*log2e/rtC; 1: k=Wk(x2+Wpos p2); 2: v=Wv x2.
// ---------------------------------------------------------------------------
#define PROJ_SMEM (1536 + 17408 + 34816)

__global__ __launch_bounds__(128, 3)
void proj_all(const float* __restrict__ x1, const float* __restrict__ p1,
              const float* __restrict__ x2, const float* __restrict__ p2,
              const float* __restrict__ Wq, const float* __restrict__ Wk,
              const float* __restrict__ Wv, const float* __restrict__ Wpos)
{
    extern __shared__ __align__(16) char smem[];
    const uint32_t sb = smem_u32(smem);
    float* wps = (float*)smem;
    __half* sX = (__half*)(smem + 1536);
    __half* sW = (__half*)(smem + 18944);

    const int tid = threadIdx.x, lane = tid & 31, w = tid >> 5;
    const int b = blockIdx.y, n0 = blockIdx.x * 64, role = blockIdx.z;

    const float* x = (role == 0) ? x1 : x2;
    const float* p = (role == 0) ? p1 : p2;
    const float* W = (role == 0) ? Wq : (role == 1) ? Wk : Wv;
    __half* outp   = (role == 0) ? g_q : (role == 1) ? g_k : g_v;
    const bool usepos = (role != 2);
    const float scale = (role == 0) ? 0.12752538963474926f : 1.0f;  // log2e/sqrt(128)

    #pragma unroll
    for (int it = 0; it < 3; it++) wps[tid + it * 128] = Wpos[tid + it * 128];
    #pragma unroll
    for (int it = 0; it < 32; it++) {
        int e4 = tid + it * 128, d = e4 >> 5, c4 = e4 & 31;
        float4 wv = *(const float4*)&W[d * 128 + c4 * 4];
        *(uint2*)&sW[d * 136 + c4 * 4] = make_uint2(packh2(wv.x, wv.y), packh2(wv.z, wv.w));
    }
    __syncthreads();

    {
        int n = tid & 63, cg = tid >> 6, gn = n0 + n;
        float pp0 = 0.f, pp1 = 0.f, pp2 = 0.f;
        if (usepos) {
            pp0 = p[(b * 3 + 0) * N_ + gn];
            pp1 = p[(b * 3 + 1) * N_ + gn];
            pp2 = p[(b * 3 + 2) * N_ + gn];
        }
        #pragma unroll
        for (int it = 0; it < 32; it++) {
            int c0 = it * 4 + cg * 2;
            float t0 = x[((size_t)(b * C_ + c0)) * N_ + gn];
            float t1 = x[((size_t)(b * C_ + c0 + 1)) * N_ + gn];
            if (usepos) {
                t0 += wps[c0*3]*pp0 + wps[c0*3+1]*pp1 + wps[c0*3+2]*pp2;
                t1 += wps[(c0+1)*3]*pp0 + wps[(c0+1)*3+1]*pp1 + wps[(c0+1)*3+2]*pp2;
            }
            *(uint32_t*)&sX[n * 136 + c0] = packh2(t0 * scale, t1 * scale);
        }
    }
    __syncthreads();

    uint32_t cf[16][2];
    #pragma unroll
    for (int g = 0; g < 16; g++) { cf[g][0] = 0u; cf[g][1] = 0u; }
    const uint32_t aoff = sb + 1536u  + (uint32_t)(w * 16 + (lane & 15)) * 272 + ((lane >> 4) & 1) * 16;
    const uint32_t woff = sb + 18944u + (uint32_t)(lane & 15) * 272 + ((lane >> 4) & 1) * 16;

    #pragma unroll
    for (int kc = 0; kc < 8; kc++) {
        uint32_t a[4];
        ldsm4(aoff + kc * 32, a[0], a[1], a[2], a[3]);
        #pragma unroll
        for (int dp = 0; dp < 8; dp++) {
            uint32_t r0, r1, r2, r3;
            ldsm4(woff + dp * 4352 + kc * 32, r0, r1, r2, r3);
            mma_h(cf[2 * dp],     a, r0, r2);
            mma_h(cf[2 * dp + 1], a, r1, r3);
        }
    }

    const int pt = n0 + w * 16 + (lane >> 2);
    #pragma unroll
    for (int dp = 0; dp < 8; dp++)
        #pragma unroll
        for (int hh = 0; hh < 2; hh++) {
            int d = dp * 16 + hh * 8 + (lane & 3) * 2;
            *(uint32_t*)&outp[((size_t)(b * N_ + pt)) * C_ + d]     = cf[2 * dp + hh][0];
            *(uint32_t*)&outp[((size_t)(b * N_ + pt + 8)) * C_ + d] = cf[2 * dp + hh][1];
        }
}

// ---------------------------------------------------------------------------
// fp16 flash attention (R9 shape) + softmax/PV interleave per 32-key half.
// TQ=128, 4 warps, warp owns 32 q-rows; key-split z=2; K,V double-buffered.
// smem = Q[0,34816) K0 K1 V0 V1 (4x17408) = 104448 -> 2 CTAs/SM.
// ---------------------------------------------------------------------------
#define ATTN_SMEM 104448

__global__ __launch_bounds__(128, 2)
void attn_h(int dummy)
{
    extern __shared__ __align__(16) char smem[];
    const uint32_t sb = smem_u32(smem);
    const int tid = threadIdx.x, lane = tid & 31, w = tid >> 5;
    const int b = blockIdx.y, n0 = blockIdx.x * TQ, kh = blockIdx.z;
    const int mbase = kh * (M_ / 2);

    const uint32_t SQ = sb;
    const uint32_t SK0 = sb + 34816u, SK1 = sb + 52224u;
    const uint32_t SV0 = sb + 69632u, SV1 = sb + 87040u;

    // prologue: Q (128 rows) + K(0) + V(0)
    #pragma unroll
    for (int it = 0; it < 16; it++) {
        int idx = tid + it * 128, r = idx >> 4, ch = idx & 15;
        cp_async16(SQ + r * 272 + ch * 16, g_q + ((size_t)(b * N_ + n0 + r)) * C_ + ch * 8);
    }
    #pragma unroll
    for (int it = 0; it < 8; it++) {
        int idx = tid + it * 128, r = idx >> 4, ch = idx & 15;
        cp_async16(SK0 + r * 272 + ch * 16, g_k + ((size_t)(b * M_ + mbase + r)) * C_ + ch * 8);
    }
    #pragma unroll
    for (int it = 0; it < 8; it++) {
        int idx = tid + it * 128, r = idx >> 4, ch = idx & 15;
        cp_async16(SV0 + r * 272 + ch * 16, g_v + ((size_t)(b * M_ + mbase + r)) * C_ + ch * 8);
    }
    asm volatile("cp.async.commit_group;" ::: "memory");
    asm volatile("cp.async.wait_group 0;" ::: "memory");
    __syncthreads();

    // Q fragments: 2 row-groups x 8 k-chunks
    uint32_t qf[8][2][4];
    #pragma unroll
    for (int g = 0; g < 2; g++) {
        const uint32_t qoff = SQ + (uint32_t)(w * 32 + g * 16 + (lane & 15)) * 272
                            + ((lane >> 4) & 1) * 16;
        #pragma unroll
        for (int kc = 0; kc < 8; kc++)
            ldsm4(qoff + kc * 32, qf[kc][g][0], qf[kc][g][1], qf[kc][g][2], qf[kc][g][3]);
    }
    const uint32_t koff = (uint32_t)(lane & 15) * 272 + ((lane >> 4) & 1) * 16;

    uint32_t og[2][16][2];
    #pragma unroll
    for (int g = 0; g < 2; g++)
        #pragma unroll
        for (int q = 0; q < 16; q++) { og[g][q][0] = 0u; og[g][q][1] = 0u; }
    float rsA[2] = {0.f, 0.f}, rsB[2] = {0.f, 0.f};

    #pragma unroll 1
    for (int j = 0; j < NTH; j++) {
        if (j > 0) {
            asm volatile("cp.async.wait_group 0;" ::: "memory");
            __syncthreads();
        }

        if (j + 1 < NTH) {
            const uint32_t kb1 = (j & 1) ? SK0 : SK1;
            const uint32_t vb1 = (j & 1) ? SV0 : SV1;
            const int m1 = mbase + (j + 1) * TK;
            #pragma unroll
            for (int it = 0; it < 8; it++) {
                int idx = tid + it * 128, r = idx >> 4, ch = idx & 15;
                cp_async16(kb1 + r * 272 + ch * 16, g_k + ((size_t)(b * M_ + m1 + r)) * C_ + ch * 8);
            }
            #pragma unroll
            for (int it = 0; it < 8; it++) {
                int idx = tid + it * 128, r = idx >> 4, ch = idx & 15;
                cp_async16(vb1 + r * 272 + ch * 16, g_v + ((size_t)(b * M_ + m1 + r)) * C_ + ch * 8);
            }
            asm volatile("cp.async.commit_group;" ::: "memory");
        }

        const uint32_t kb = (j & 1) ? SK1 : SK0;
        const uint32_t vb = (j & 1) ? SV1 : SV0;

        // S = Q K^T (64 keys x 32 rows), f16 accum; each K frag feeds 4 MMAs
        uint32_t s[2][8][2];
        #pragma unroll
        for (int g = 0; g < 2; g++)
            #pragma unroll
            for (int q = 0; q < 8; q++) { s[g][q][0] = 0u; s[g][q][1] = 0u; }
        #pragma unroll
        for (int kc = 0; kc < 8; kc++) {
            #pragma unroll
            for (int mg = 0; mg < 4; mg++) {
                uint32_t r0, r1, r2, r3;
                ldsm4(kb + mg * 4352 + kc * 32 + koff, r0, r1, r2, r3);
                #pragma unroll
                for (int g = 0; g < 2; g++) {
                    mma_h(s[g][2 * mg],     qf[kc][g], r0, r2);
                    mma_h(s[g][2 * mg + 1], qf[kc][g], r1, r3);
                }
            }
        }

        // interleave: softmax(half h) then PV(half h) — ex2 of h=1 overlaps PV(h=0)
        #pragma unroll
        for (int h = 0; h < 2; h++) {
            #pragma unroll
            for (int g = 0; g < 2; g++) {
                #pragma unroll
                for (int q = 4 * h; q < 4 * h + 4; q++) {
                    s[g][q][0] = ex2h2(s[g][q][0]);
                    s[g][q][1] = ex2h2(s[g][q][1]);
                }
                uint32_t tA = hadd2u(hadd2u(s[g][4*h][0], s[g][4*h+1][0]),
                                     hadd2u(s[g][4*h+2][0], s[g][4*h+3][0]));
                uint32_t tB = hadd2u(hadd2u(s[g][4*h][1], s[g][4*h+1][1]),
                                     hadd2u(s[g][4*h+2][1], s[g][4*h+3][1]));
                rsA[g] += hsum2(tA);
                rsB[g] += hsum2(tB);
            }
            #pragma unroll
            for (int km = 2 * h; km < 2 * h + 2; km++) {
                uint32_t a0[4] = { s[0][2*km][0], s[0][2*km][1], s[0][2*km+1][0], s[0][2*km+1][1] };
                uint32_t a1[4] = { s[1][2*km][0], s[1][2*km][1], s[1][2*km+1][0], s[1][2*km+1][1] };
                #pragma unroll
                for (int cp = 0; cp < 8; cp++) {
                    uint32_t r0, r1, r2, r3;
                    ldsm4t(vb + km * 4352 + cp * 32 + koff, r0, r1, r2, r3);
                    mma_h(og[0][2 * cp],     a0, r0, r1);
                    mma_h(og[0][2 * cp + 1], a0, r2, r3);
                    mma_h(og[1][2 * cp],     a1, r0, r1);
                    mma_h(og[1][2 * cp + 1], a1, r2, r3);
                }
            }
        }
    }

    // quad-reduce row sums; write partials
    #pragma unroll
    for (int g = 0; g < 2; g++) {
        rsA[g] += __shfl_xor_sync(0xffffffffu, rsA[g], 1);
        rsA[g] += __shfl_xor_sync(0xffffffffu, rsA[g], 2);
        rsB[g] += __shfl_xor_sync(0xffffffffu, rsB[g], 1);
        rsB[g] += __shfl_xor_sync(0xffffffffu, rsB[g], 2);
    }

    #pragma unroll
    for (int g = 0; g < 2; g++) {
        const int rA = w * 32 + g * 16 + (lane >> 2);
        if ((lane & 3) == 0) {
            g_rs[kh][(size_t)b * N_ + n0 + rA]     = rsA[g];
            g_rs[kh][(size_t)b * N_ + n0 + rA + 8] = rsB[g];
        }
        #pragma unroll
        for (int cg = 0; cg < 16; cg++) {
            int c = cg * 8 + (lane & 3) * 2;
            *(uint32_t*)&g_op[kh][((size_t)(b * N_ + n0 + rA)) * C_ + c]     = og[g][cg][0];
            *(uint32_t*)&g_op[kh][((size_t)(b * N_ + n0 + rA + 8)) * C_ + c] = og[g][cg][1];
        }
    }
}

// ---------------------------------------------------------------------------
// Merge: out[b][n][c] = (O0+O1)[n][c] / (rs0+rs1)[n] + x1[b][c][n].
// 512 CTAs x 128 threads, 32 rows each; all gmem loads front-batched.
// ---------------------------------------------------------------------------
__global__ __launch_bounds__(128)
void merge_out(const float* __restrict__ x1, float* __restrict__ outp)
{
    __shared__ float x1s[128 * 36];
    const int tid = threadIdx.x;
    const int b = blockIdx.y, n0 = blockIdx.x * 32;

    // stage x1 [c 0..127][n_local 0..31]
    #pragma unroll
    for (int it = 0; it < 8; it++) {
        int idx = tid + it * 128, r = idx >> 3, cc = idx & 7;
        *(float4*)&x1s[r * 36 + cc * 4] =
            *(const float4*)(x1 + ((size_t)(b * C_ + r)) * N_ + n0 + cc * 4);
    }

    const int nl = tid >> 2, n = n0 + nl, chunk = tid & 3;

    // front-batch ALL partial loads (8 uint4) + row sums before any compute
    uint4 h0[4], h1[4];
    #pragma unroll
    for (int i = 0; i < 4; i++) {
        int c = chunk * 32 + i * 8;
        h0[i] = *(const uint4*)&g_op[0][((size_t)(b * N_ + n)) * C_ + c];
        h1[i] = *(const uint4*)&g_op[1][((size_t)(b * N_ + n)) * C_ + c];
    }
    const float r0 = g_rs[0][(size_t)b * N_ + n];
    const float r1 = g_rs[1][(size_t)b * N_ + n];
    const float inv = 1.0f / (r0 + r1);
    __syncthreads();

    #pragma unroll
    for (int i = 0; i < 4; i++) {
        int c = chunk * 32 + i * 8;
        const uint32_t* a = (const uint32_t*)&h0[i];
        const uint32_t* d = (const uint32_t*)&h1[i];
        float4 o0, o1;
        float2 f, g2;
        f = h2f2(a[0]); g2 = h2f2(d[0]);
        o0.x = (f.x + g2.x) * inv + x1s[(c + 0) * 36 + nl];
        o0.y = (f.y + g2.y) * inv + x1s[(c + 1) * 36 + nl];
        f = h2f2(a[1]); g2 = h2f2(d[1]);
        o0.z = (f.x + g2.x) * inv + x1s[(c + 2) * 36 + nl];
        o0.w = (f.y + g2.y) * inv + x1s[(c + 3) * 36 + nl];
        f = h2f2(a[2]); g2 = h2f2(d[2]);
        o1.x = (f.x + g2.x) * inv + x1s[(c + 4) * 36 + nl];
        o1.y = (f.y + g2.y) * inv + x1s[(c + 5) * 36 + nl];
        f = h2f2(a[3]); g2 = h2f2(d[3]);
        o1.z = (f.x + g2.x) * inv + x1s[(c + 6) * 36 + nl];
        o1.w = (f.y + g2.y) * inv + x1s[(c + 7) * 36 + nl];
        *(float4*)&outp[((size_t)(b * N_ + n)) * C_ + c]     = o0;
        *(float4*)&outp[((size_t)(b * N_ + n)) * C_ + c + 4] = o1;
    }
}

// ---------------------------------------------------------------------------
extern "C" void kernel_launch(void* const* d_in, const int* in_sizes, int n_in,
                              void* d_out, int out_size)
{
    const float* x1   = (const float*)d_in[0];
    const float* p1   = (const float*)d_in[1];
    const float* x2   = (const float*)d_in[2];
    const float* p2   = (const float*)d_in[3];
    const float* Wq   = (const float*)d_in[4];
    const float* Wk   = (const float*)d_in[5];
    const float* Wv   = (const float*)d_in[6];
    const float* Wpos = (const float*)d_in[7];
    float* out = (float*)d_out;

    cudaFuncSetAttribute(proj_all, cudaFuncAttributeMaxDynamicSharedMemorySize, PROJ_SMEM);
    cudaFuncSetAttribute(attn_h,   cudaFuncAttributeMaxDynamicSharedMemorySize, ATTN_SMEM);

    dim3 gproj(64, B_, 3), bproj(128);
    proj_all<<<gproj, bproj, PROJ_SMEM>>>(x1, p1, x2, p2, Wq, Wk, Wv, Wpos);

    dim3 gattn(N_ / TQ, B_, 2), battn(128);
    attn_h<<<gattn, battn, ATTN_SMEM>>>(0);

    dim3 gmerge(N_ / 32, B_), bmerge(128);
    merge_out<<<gmerge, bmerge>>>(x1, out);
}